// round 9
// baseline (speedup 1.0000x reference)
#include <cuda_runtime.h>
#include <math.h>

// Problem constants
#define DD 1024
#define SS 2048
#define BB 8
#define BSROWS (BB * SS)   // 16384

typedef long long ll;

// ---------------- scratch (static device globals: allocation-free) ----------
__device__ __align__(16) float g_M[DD * DD];                 // Wq2 @ Wk2^T      (4 MB)
__device__ __align__(16) float g_tvec[DD];                   // Wk2 @ bq2
__device__ __align__(16) float g_vb1[BB * DD];               // x1_b @ Wv[:D] + bv
__device__ __align__(16) float g_G[(ll)BB * SS * DD];        // X2 @ M           (64 MB)
__device__ __align__(16) float g_V[(ll)BB * SS * DD];        // value tokens     (64 MB)
__device__ __align__(16) float g_sw[BB * SS];                // s * (x_k . tvec)
__device__ __align__(16) float g_A[(ll)BB * SS * SS];        // scores / probs   (128 MB)
__device__ __align__(16) float g_part[64 * DD];              // Vsum partials
__device__ __align__(16) float g_negV[BB * DD];              // -(alpha/S)*Vsum

// ---------------- tiled fp32 GEMM: C = scale * (A @ B or A @ B^T) + bias[n] --
// Block tile 128x128, K-tile 8, 256 threads, 8x8 per-thread, double-buffered.
#define BM 128
#define BN 128
#define BK 8

template <bool NT>
__global__ __launch_bounds__(256, 2)
void gemm_tiled(const float* __restrict__ Ag, const float* __restrict__ Bg,
                float* __restrict__ Cg,
                int M, int N, int K,
                ll sA, ll sB, ll sC,
                float scale, const float* __restrict__ biasG, ll sBias)
{
    const int bz = blockIdx.z;
    const float* A = Ag + (ll)bz * sA;
    const float* Bm = Bg + (ll)bz * sB;
    float* C = Cg + (ll)bz * sC;
    const float* bias = biasG ? (biasG + (ll)bz * sBias) : nullptr;

    __shared__ __align__(16) float As[2][BK][BM];
    __shared__ __align__(16) float Bs[2][BK][BN];

    const int tid = threadIdx.x;
    const int m0 = blockIdx.y * BM;
    const int n0 = blockIdx.x * BN;

    // A tile load: 128 rows x 8 k, one float4 per thread
    const int a_row = tid >> 1;
    const int a_k   = (tid & 1) * 4;
    // B tile load mapping
    const int b_r = NT ? (tid >> 1) : (tid >> 5);        // NT: n-row ; NN: k-row
    const int b_c = NT ? ((tid & 1) * 4) : ((tid & 31) * 4); // NT: k ; NN: n

    const int tx = tid & 15;      // n
    const int ty = tid >> 4;      // m
    const int tm = ty * 8;
    const int tn = tx * 8;

    float acc[8][8];
#pragma unroll
    for (int i = 0; i < 8; i++)
#pragma unroll
        for (int j = 0; j < 8; j++) acc[i][j] = 0.f;

    auto loadA = [&](int buf, int k0) {
        float4 v = *reinterpret_cast<const float4*>(A + (ll)(m0 + a_row) * K + k0 + a_k);
        As[buf][a_k + 0][a_row] = v.x;
        As[buf][a_k + 1][a_row] = v.y;
        As[buf][a_k + 2][a_row] = v.z;
        As[buf][a_k + 3][a_row] = v.w;
    };
    auto loadB = [&](int buf, int k0) {
        if (NT) {
            float4 v = *reinterpret_cast<const float4*>(Bm + (ll)(n0 + b_r) * K + k0 + b_c);
            Bs[buf][b_c + 0][b_r] = v.x;
            Bs[buf][b_c + 1][b_r] = v.y;
            Bs[buf][b_c + 2][b_r] = v.z;
            Bs[buf][b_c + 3][b_r] = v.w;
        } else {
            float4 v = *reinterpret_cast<const float4*>(Bm + (ll)(k0 + b_r) * N + n0 + b_c);
            *reinterpret_cast<float4*>(&Bs[buf][b_r][b_c]) = v;
        }
    };

    loadA(0, 0);
    loadB(0, 0);
    __syncthreads();

    const int nk = K / BK;
    for (int kt = 0; kt < nk; kt++) {
        const int cur = kt & 1;
        if (kt + 1 < nk) {
            loadA(cur ^ 1, (kt + 1) * BK);
            loadB(cur ^ 1, (kt + 1) * BK);
        }
#pragma unroll
        for (int kk = 0; kk < BK; kk++) {
            float ar[8], br[8];
            float4 a0 = *reinterpret_cast<const float4*>(&As[cur][kk][tm]);
            float4 a1 = *reinterpret_cast<const float4*>(&As[cur][kk][tm + 4]);
            float4 b0 = *reinterpret_cast<const float4*>(&Bs[cur][kk][tn]);
            float4 b1 = *reinterpret_cast<const float4*>(&Bs[cur][kk][tn + 4]);
            ar[0]=a0.x; ar[1]=a0.y; ar[2]=a0.z; ar[3]=a0.w;
            ar[4]=a1.x; ar[5]=a1.y; ar[6]=a1.z; ar[7]=a1.w;
            br[0]=b0.x; br[1]=b0.y; br[2]=b0.z; br[3]=b0.w;
            br[4]=b1.x; br[5]=b1.y; br[6]=b1.z; br[7]=b1.w;
#pragma unroll
            for (int i = 0; i < 8; i++)
#pragma unroll
                for (int j = 0; j < 8; j++)
                    acc[i][j] = fmaf(ar[i], br[j], acc[i][j]);
        }
        __syncthreads();
    }

    // epilogue: C = acc*scale + bias[n]
#pragma unroll
    for (int i = 0; i < 8; i++) {
        const ll row = m0 + tm + i;
#pragma unroll
        for (int j = 0; j < 8; j += 4) {
            float4 v;
            v.x = acc[i][j + 0] * scale;
            v.y = acc[i][j + 1] * scale;
            v.z = acc[i][j + 2] * scale;
            v.w = acc[i][j + 3] * scale;
            if (bias) {
                v.x += bias[n0 + tn + j + 0];
                v.y += bias[n0 + tn + j + 1];
                v.z += bias[n0 + tn + j + 2];
                v.w += bias[n0 + tn + j + 3];
            }
            *reinterpret_cast<float4*>(C + row * N + n0 + tn + j) = v;
        }
    }
}

// ---------------- warp-per-row dot: out[r] = scale * (X[r,:1024] . vec) -----
__global__ void rowdot_kernel(const float* __restrict__ X, const float* __restrict__ vec,
                              float* __restrict__ out, int nrows, float scale)
{
    const int warp = (blockIdx.x * blockDim.x + threadIdx.x) >> 5;
    const int lane = threadIdx.x & 31;
    if (warp >= nrows) return;
    const float4* r = reinterpret_cast<const float4*>(X + (ll)warp * DD);
    const float4* v = reinterpret_cast<const float4*>(vec);
    float acc = 0.f;
#pragma unroll
    for (int i = 0; i < 8; i++) {
        float4 a = r[lane + 32 * i];
        float4 b = v[lane + 32 * i];
        acc += a.x * b.x + a.y * b.y + a.z * b.z + a.w * b.w;
    }
#pragma unroll
    for (int off = 16; off; off >>= 1)
        acc += __shfl_xor_sync(0xffffffffu, acc, off);
    if (lane == 0) out[warp] = scale * acc;
}

// ---------------- vb1[b,o] = X1[b,:] @ Wv[:D, o] + bv[o] --------------------
__global__ void vb1_kernel(const float* __restrict__ X1, const float* __restrict__ Wv,
                           const float* __restrict__ bv, float* __restrict__ vb1)
{
    __shared__ float x1s[BB * DD];
    const int tid = threadIdx.x;  // 128
    for (int i = tid; i < BB * DD; i += 128) x1s[i] = X1[i];
    __syncthreads();
    const int o = blockIdx.x * 128 + tid;
    float acc[BB];
#pragma unroll
    for (int b = 0; b < BB; b++) acc[b] = 0.f;
    for (int i = 0; i < DD; i++) {
        const float wv = Wv[(ll)i * DD + o];
#pragma unroll
        for (int b = 0; b < BB; b++) acc[b] = fmaf(x1s[b * DD + i], wv, acc[b]);
    }
    const float bvo = bv[o];
#pragma unroll
    for (int b = 0; b < BB; b++) vb1[b * DD + o] = acc[b] + bvo;
}

// ---------------- row softmax over 2048 columns, in place -------------------
__global__ __launch_bounds__(256) void softmax_rows(float* __restrict__ A)
{
    float* p = A + (ll)blockIdx.x * SS;
    const int tid = threadIdx.x;
    const int lane = tid & 31, wid = tid >> 5;
    float4* pv = reinterpret_cast<float4*>(p);
    float4 v0 = pv[tid];
    float4 v1 = pv[tid + 256];

    float m = fmaxf(fmaxf(fmaxf(v0.x, v0.y), fmaxf(v0.z, v0.w)),
                    fmaxf(fmaxf(v1.x, v1.y), fmaxf(v1.z, v1.w)));
#pragma unroll
    for (int off = 16; off; off >>= 1) m = fmaxf(m, __shfl_xor_sync(0xffffffffu, m, off));
    __shared__ float smax[8], ssum[8];
    if (lane == 0) smax[wid] = m;
    __syncthreads();
    float mall = smax[0];
#pragma unroll
    for (int i = 1; i < 8; i++) mall = fmaxf(mall, smax[i]);

    v0.x = expf(v0.x - mall); v0.y = expf(v0.y - mall);
    v0.z = expf(v0.z - mall); v0.w = expf(v0.w - mall);
    v1.x = expf(v1.x - mall); v1.y = expf(v1.y - mall);
    v1.z = expf(v1.z - mall); v1.w = expf(v1.w - mall);

    float s = v0.x + v0.y + v0.z + v0.w + v1.x + v1.y + v1.z + v1.w;
#pragma unroll
    for (int off = 16; off; off >>= 1) s += __shfl_xor_sync(0xffffffffu, s, off);
    if (lane == 0) ssum[wid] = s;
    __syncthreads();
    float tot = 0.f;
#pragma unroll
    for (int i = 0; i < 8; i++) tot += ssum[i];
    const float inv = 1.f / tot;

    v0.x *= inv; v0.y *= inv; v0.z *= inv; v0.w *= inv;
    v1.x *= inv; v1.y *= inv; v1.z *= inv; v1.w *= inv;
    pv[tid] = v0;
    pv[tid + 256] = v1;
}

// ---------------- Vsum: partials then reduce+scale --------------------------
__global__ void vsum_part(const float* __restrict__ V, float* __restrict__ part)
{
    const int b = blockIdx.x >> 3, c = blockIdx.x & 7;
    const int o = threadIdx.x;  // 1024
    const float* base = V + ((ll)(b * SS + c * 256)) * DD + o;
    float acc = 0.f;
#pragma unroll 8
    for (int s = 0; s < 256; s++) acc += base[(ll)s * DD];
    part[(ll)blockIdx.x * DD + o] = acc;
}

__global__ void vsum_reduce(const float* __restrict__ part, const float* __restrict__ alpha,
                            float* __restrict__ negV)
{
    const int b = blockIdx.x, o = threadIdx.x;
    float acc = 0.f;
#pragma unroll
    for (int c = 0; c < 8; c++) acc += part[(ll)(b * 8 + c) * DD + o];
    negV[b * DD + o] = -(alpha[0] / (float)SS) * acc;
}

// ---------------- launch ----------------------------------------------------
extern "C" void kernel_launch(void* const* d_in, const int* in_sizes, int n_in,
                              void* d_out, int out_size)
{
    (void)in_sizes; (void)n_in; (void)out_size;
    const float* X1   = (const float*)d_in[0];
    const float* X2   = (const float*)d_in[1];
    const float* Wq2  = (const float*)d_in[4];
    const float* bq2  = (const float*)d_in[5];
    const float* Wk2  = (const float*)d_in[8];
    const float* Wv   = (const float*)d_in[10];
    const float* bv   = (const float*)d_in[11];
    const float* alph = (const float*)d_in[12];
    float* out = (float*)d_out;

    const float s = 0.03125f;  // 1/sqrt(1024)

    void* p;
    cudaGetSymbolAddress(&p, g_M);    float* pM    = (float*)p;
    cudaGetSymbolAddress(&p, g_tvec); float* ptvec = (float*)p;
    cudaGetSymbolAddress(&p, g_vb1);  float* pvb1  = (float*)p;
    cudaGetSymbolAddress(&p, g_G);    float* pG    = (float*)p;
    cudaGetSymbolAddress(&p, g_V);    float* pV    = (float*)p;
    cudaGetSymbolAddress(&p, g_sw);   float* psw   = (float*)p;
    cudaGetSymbolAddress(&p, g_A);    float* pA    = (float*)p;
    cudaGetSymbolAddress(&p, g_part); float* ppart = (float*)p;
    cudaGetSymbolAddress(&p, g_negV); float* pnegV = (float*)p;

    const dim3 blk(256);

    // 1. M = Wq2 @ Wk2^T   (row-i(Wq2) . row-j(Wk2))
    gemm_tiled<true><<<dim3(DD / BN, DD / BM, 1), blk>>>(
        Wq2, Wk2, pM, DD, DD, DD, 0, 0, 0, 1.f, nullptr, 0);

    // 2. tvec = Wk2 @ bq2
    rowdot_kernel<<<DD / 8, 256>>>(Wk2, bq2, ptvec, DD, 1.f);

    // 3. vb1[b,:] = X1[b] @ Wv[:D] + bv
    vb1_kernel<<<DD / 128, 128>>>(X1, Wv, bv, pvb1);

    // 4. G = X2 @ M        (per batch, shared B)
    gemm_tiled<false><<<dim3(DD / BN, SS / BM, BB), blk>>>(
        X2, pM, pG, SS, DD, DD, (ll)SS * DD, 0, (ll)SS * DD, 1.f, nullptr, 0);

    // 5. V = X2 @ Wv[D:] + vb1[b]
    gemm_tiled<false><<<dim3(DD / BN, SS / BM, BB), blk>>>(
        X2, Wv + (ll)DD * DD, pV, SS, DD, DD, (ll)SS * DD, 0, (ll)SS * DD, 1.f, pvb1, DD);

    // 6. sw[b,k] = s * (X2[b,k] . tvec)
    rowdot_kernel<<<BSROWS / 8, 256>>>(X2, ptvec, psw, BSROWS, s);

    // 7. scores = s * (G @ X2^T) + sw[k]   (per batch, NT)
    gemm_tiled<true><<<dim3(SS / BN, SS / BM, BB), blk>>>(
        pG, X2, pA, SS, SS, DD, (ll)SS * DD, (ll)SS * DD, (ll)SS * SS, s, psw, SS);

    // 8. P = softmax(scores) rows, in place
    softmax_rows<<<BSROWS, 256>>>(pA);

    // 9. negVsum[b,:] = -(alpha/S) * sum_k V[b,k,:]
    vsum_part<<<64, 1024>>>(pV, ppart);
    vsum_reduce<<<BB, 1024>>>(ppart, alph, pnegV);

    // 10. out = P @ V + negVsum[b]   (per batch)
    gemm_tiled<false><<<dim3(DD / BN, SS / BM, BB), blk>>>(
        pA, pV, out, SS, DD, SS, (ll)SS * SS, (ll)SS * DD, (ll)SS * DD, 1.f, pnegV, DD);
}

// round 10
// speedup vs baseline: 1.0014x; 1.0014x over previous
#include <cuda_runtime.h>
#include <math.h>

// Problem constants
#define DD 1024
#define SS 2048
#define BB 8
#define BSROWS (BB * SS)   // 16384

typedef long long ll;

// ---------------- scratch (static device globals: allocation-free) ----------
__device__ __align__(16) float g_M[DD * DD];                 // Wq2 @ Wk2^T      (4 MB)
__device__ __align__(16) float g_tvec[DD];                   // Wk2 @ bq2
__device__ __align__(16) float g_vb1[BB * DD];               // x1_b @ Wv[:D] + bv
__device__ __align__(16) float g_G[(ll)BB * SS * DD];        // X2 @ M           (64 MB)
__device__ __align__(16) float g_V[(ll)BB * SS * DD];        // value tokens     (64 MB)
__device__ __align__(16) float g_sw[BB * SS];                // s * (x_k . tvec)
__device__ __align__(16) float g_A[(ll)BB * SS * SS];        // scores / probs   (128 MB)
__device__ __align__(16) float g_part[64 * DD];              // Vsum partials
__device__ __align__(16) float g_negV[BB * DD];              // -(alpha/S)*Vsum

// ---------------- tiled fp32 GEMM: C = scale * (A @ B or A @ B^T) + bias[n] --
// Block tile 128x128, K-tile 8, 256 threads, 8x8 per-thread, double-buffered.
#define BM 128
#define BN 128
#define BK 8

template <bool NT>
__global__ __launch_bounds__(256, 2)
void gemm_tiled(const float* __restrict__ Ag, const float* __restrict__ Bg,
                float* __restrict__ Cg,
                int M, int N, int K,
                ll sA, ll sB, ll sC,
                float scale, const float* __restrict__ biasG, ll sBias)
{
    const int bz = blockIdx.z;
    const float* A = Ag + (ll)bz * sA;
    const float* Bm = Bg + (ll)bz * sB;
    float* C = Cg + (ll)bz * sC;
    const float* bias = biasG ? (biasG + (ll)bz * sBias) : nullptr;

    __shared__ __align__(16) float As[2][BK][BM];
    __shared__ __align__(16) float Bs[2][BK][BN];

    const int tid = threadIdx.x;
    const int m0 = blockIdx.y * BM;
    const int n0 = blockIdx.x * BN;

    // A tile load: 128 rows x 8 k, one float4 per thread
    const int a_row = tid >> 1;
    const int a_k   = (tid & 1) * 4;
    // B tile load mapping
    const int b_r = NT ? (tid >> 1) : (tid >> 5);        // NT: n-row ; NN: k-row
    const int b_c = NT ? ((tid & 1) * 4) : ((tid & 31) * 4); // NT: k ; NN: n

    const int tx = tid & 15;      // n
    const int ty = tid >> 4;      // m
    const int tm = ty * 8;
    const int tn = tx * 8;

    float acc[8][8];
#pragma unroll
    for (int i = 0; i < 8; i++)
#pragma unroll
        for (int j = 0; j < 8; j++) acc[i][j] = 0.f;

    auto loadA = [&](int buf, int k0) {
        float4 v = *reinterpret_cast<const float4*>(A + (ll)(m0 + a_row) * K + k0 + a_k);
        As[buf][a_k + 0][a_row] = v.x;
        As[buf][a_k + 1][a_row] = v.y;
        As[buf][a_k + 2][a_row] = v.z;
        As[buf][a_k + 3][a_row] = v.w;
    };
    auto loadB = [&](int buf, int k0) {
        if (NT) {
            float4 v = *reinterpret_cast<const float4*>(Bm + (ll)(n0 + b_r) * K + k0 + b_c);
            Bs[buf][b_c + 0][b_r] = v.x;
            Bs[buf][b_c + 1][b_r] = v.y;
            Bs[buf][b_c + 2][b_r] = v.z;
            Bs[buf][b_c + 3][b_r] = v.w;
        } else {
            float4 v = *reinterpret_cast<const float4*>(Bm + (ll)(k0 + b_r) * N + n0 + b_c);
            *reinterpret_cast<float4*>(&Bs[buf][b_r][b_c]) = v;
        }
    };

    loadA(0, 0);
    loadB(0, 0);
    __syncthreads();

    const int nk = K / BK;
    for (int kt = 0; kt < nk; kt++) {
        const int cur = kt & 1;
        if (kt + 1 < nk) {
            loadA(cur ^ 1, (kt + 1) * BK);
            loadB(cur ^ 1, (kt + 1) * BK);
        }
#pragma unroll
        for (int kk = 0; kk < BK; kk++) {
            float ar[8], br[8];
            float4 a0 = *reinterpret_cast<const float4*>(&As[cur][kk][tm]);
            float4 a1 = *reinterpret_cast<const float4*>(&As[cur][kk][tm + 4]);
            float4 b0 = *reinterpret_cast<const float4*>(&Bs[cur][kk][tn]);
            float4 b1 = *reinterpret_cast<const float4*>(&Bs[cur][kk][tn + 4]);
            ar[0]=a0.x; ar[1]=a0.y; ar[2]=a0.z; ar[3]=a0.w;
            ar[4]=a1.x; ar[5]=a1.y; ar[6]=a1.z; ar[7]=a1.w;
            br[0]=b0.x; br[1]=b0.y; br[2]=b0.z; br[3]=b0.w;
            br[4]=b1.x; br[5]=b1.y; br[6]=b1.z; br[7]=b1.w;
#pragma unroll
            for (int i = 0; i < 8; i++)
#pragma unroll
                for (int j = 0; j < 8; j++)
                    acc[i][j] = fmaf(ar[i], br[j], acc[i][j]);
        }
        __syncthreads();
    }

    // epilogue: C = acc*scale + bias[n]
#pragma unroll
    for (int i = 0; i < 8; i++) {
        const ll row = m0 + tm + i;
#pragma unroll
        for (int j = 0; j < 8; j += 4) {
            float4 v;
            v.x = acc[i][j + 0] * scale;
            v.y = acc[i][j + 1] * scale;
            v.z = acc[i][j + 2] * scale;
            v.w = acc[i][j + 3] * scale;
            if (bias) {
                v.x += bias[n0 + tn + j + 0];
                v.y += bias[n0 + tn + j + 1];
                v.z += bias[n0 + tn + j + 2];
                v.w += bias[n0 + tn + j + 3];
            }
            *reinterpret_cast<float4*>(C + row * N + n0 + tn + j) = v;
        }
    }
}

// ---------------- warp-per-row dot: out[r] = scale * (X[r,:1024] . vec) -----
__global__ void rowdot_kernel(const float* __restrict__ X, const float* __restrict__ vec,
                              float* __restrict__ out, int nrows, float scale)
{
    const int warp = (blockIdx.x * blockDim.x + threadIdx.x) >> 5;
    const int lane = threadIdx.x & 31;
    if (warp >= nrows) return;
    const float4* r = reinterpret_cast<const float4*>(X + (ll)warp * DD);
    const float4* v = reinterpret_cast<const float4*>(vec);
    float acc = 0.f;
#pragma unroll
    for (int i = 0; i < 8; i++) {
        float4 a = r[lane + 32 * i];
        float4 b = v[lane + 32 * i];
        acc += a.x * b.x + a.y * b.y + a.z * b.z + a.w * b.w;
    }
#pragma unroll
    for (int off = 16; off; off >>= 1)
        acc += __shfl_xor_sync(0xffffffffu, acc, off);
    if (lane == 0) out[warp] = scale * acc;
}

// ---------------- vb1[b,o] = X1[b,:] @ Wv[:D, o] + bv[o] --------------------
__global__ void vb1_kernel(const float* __restrict__ X1, const float* __restrict__ Wv,
                           const float* __restrict__ bv, float* __restrict__ vb1)
{
    __shared__ float x1s[BB * DD];
    const int tid = threadIdx.x;  // 128
    for (int i = tid; i < BB * DD; i += 128) x1s[i] = X1[i];
    __syncthreads();
    const int o = blockIdx.x * 128 + tid;
    float acc[BB];
#pragma unroll
    for (int b = 0; b < BB; b++) acc[b] = 0.f;
    for (int i = 0; i < DD; i++) {
        const float wv = Wv[(ll)i * DD + o];
#pragma unroll
        for (int b = 0; b < BB; b++) acc[b] = fmaf(x1s[b * DD + i], wv, acc[b]);
    }
    const float bvo = bv[o];
#pragma unroll
    for (int b = 0; b < BB; b++) vb1[b * DD + o] = acc[b] + bvo;
}

// ---------------- row softmax over 2048 columns, in place -------------------
__global__ __launch_bounds__(256) void softmax_rows(float* __restrict__ A)
{
    float* p = A + (ll)blockIdx.x * SS;
    const int tid = threadIdx.x;
    const int lane = tid & 31, wid = tid >> 5;
    float4* pv = reinterpret_cast<float4*>(p);
    float4 v0 = pv[tid];
    float4 v1 = pv[tid + 256];

    float m = fmaxf(fmaxf(fmaxf(v0.x, v0.y), fmaxf(v0.z, v0.w)),
                    fmaxf(fmaxf(v1.x, v1.y), fmaxf(v1.z, v1.w)));
#pragma unroll
    for (int off = 16; off; off >>= 1) m = fmaxf(m, __shfl_xor_sync(0xffffffffu, m, off));
    __shared__ float smax[8], ssum[8];
    if (lane == 0) smax[wid] = m;
    __syncthreads();
    float mall = smax[0];
#pragma unroll
    for (int i = 1; i < 8; i++) mall = fmaxf(mall, smax[i]);

    v0.x = expf(v0.x - mall); v0.y = expf(v0.y - mall);
    v0.z = expf(v0.z - mall); v0.w = expf(v0.w - mall);
    v1.x = expf(v1.x - mall); v1.y = expf(v1.y - mall);
    v1.z = expf(v1.z - mall); v1.w = expf(v1.w - mall);

    float s = v0.x + v0.y + v0.z + v0.w + v1.x + v1.y + v1.z + v1.w;
#pragma unroll
    for (int off = 16; off; off >>= 1) s += __shfl_xor_sync(0xffffffffu, s, off);
    if (lane == 0) ssum[wid] = s;
    __syncthreads();
    float tot = 0.f;
#pragma unroll
    for (int i = 0; i < 8; i++) tot += ssum[i];
    const float inv = 1.f / tot;

    v0.x *= inv; v0.y *= inv; v0.z *= inv; v0.w *= inv;
    v1.x *= inv; v1.y *= inv; v1.z *= inv; v1.w *= inv;
    pv[tid] = v0;
    pv[tid + 256] = v1;
}

// ---------------- Vsum: partials then reduce+scale --------------------------
__global__ void vsum_part(const float* __restrict__ V, float* __restrict__ part)
{
    const int b = blockIdx.x >> 3, c = blockIdx.x & 7;
    const int o = threadIdx.x;  // 1024
    const float* base = V + ((ll)(b * SS + c * 256)) * DD + o;
    float acc = 0.f;
#pragma unroll 8
    for (int s = 0; s < 256; s++) acc += base[(ll)s * DD];
    part[(ll)blockIdx.x * DD + o] = acc;
}

__global__ void vsum_reduce(const float* __restrict__ part, const float* __restrict__ alpha,
                            float* __restrict__ negV)
{
    const int b = blockIdx.x, o = threadIdx.x;
    float acc = 0.f;
#pragma unroll
    for (int c = 0; c < 8; c++) acc += part[(ll)(b * 8 + c) * DD + o];
    negV[b * DD + o] = -(alpha[0] / (float)SS) * acc;
}

// ---------------- launch ----------------------------------------------------
extern "C" void kernel_launch(void* const* d_in, const int* in_sizes, int n_in,
                              void* d_out, int out_size)
{
    (void)in_sizes; (void)n_in; (void)out_size;
    const float* X1   = (const float*)d_in[0];
    const float* X2   = (const float*)d_in[1];
    const float* Wq2  = (const float*)d_in[4];
    const float* bq2  = (const float*)d_in[5];
    const float* Wk2  = (const float*)d_in[8];
    const float* Wv   = (const float*)d_in[10];
    const float* bv   = (const float*)d_in[11];
    const float* alph = (const float*)d_in[12];
    float* out = (float*)d_out;

    const float s = 0.03125f;  // 1/sqrt(1024)

    void* p;
    cudaGetSymbolAddress(&p, g_M);    float* pM    = (float*)p;
    cudaGetSymbolAddress(&p, g_tvec); float* ptvec = (float*)p;
    cudaGetSymbolAddress(&p, g_vb1);  float* pvb1  = (float*)p;
    cudaGetSymbolAddress(&p, g_G);    float* pG    = (float*)p;
    cudaGetSymbolAddress(&p, g_V);    float* pV    = (float*)p;
    cudaGetSymbolAddress(&p, g_sw);   float* psw   = (float*)p;
    cudaGetSymbolAddress(&p, g_A);    float* pA    = (float*)p;
    cudaGetSymbolAddress(&p, g_part); float* ppart = (float*)p;
    cudaGetSymbolAddress(&p, g_negV); float* pnegV = (float*)p;

    const dim3 blk(256);

    // 1. M = Wq2 @ Wk2^T   (row-i(Wq2) . row-j(Wk2))
    gemm_tiled<true><<<dim3(DD / BN, DD / BM, 1), blk>>>(
        Wq2, Wk2, pM, DD, DD, DD, 0, 0, 0, 1.f, nullptr, 0);

    // 2. tvec = Wk2 @ bq2
    rowdot_kernel<<<DD / 8, 256>>>(Wk2, bq2, ptvec, DD, 1.f);

    // 3. vb1[b,:] = X1[b] @ Wv[:D] + bv
    vb1_kernel<<<DD / 128, 128>>>(X1, Wv, bv, pvb1);

    // 4. G = X2 @ M        (per batch, shared B)
    gemm_tiled<false><<<dim3(DD / BN, SS / BM, BB), blk>>>(
        X2, pM, pG, SS, DD, DD, (ll)SS * DD, 0, (ll)SS * DD, 1.f, nullptr, 0);

    // 5. V = X2 @ Wv[D:] + vb1[b]
    gemm_tiled<false><<<dim3(DD / BN, SS / BM, BB), blk>>>(
        X2, Wv + (ll)DD * DD, pV, SS, DD, DD, (ll)SS * DD, 0, (ll)SS * DD, 1.f, pvb1, DD);

    // 6. sw[b,k] = s * (X2[b,k] . tvec)
    rowdot_kernel<<<BSROWS / 8, 256>>>(X2, ptvec, psw, BSROWS, s);

    // 7. scores = s * (G @ X2^T) + sw[k]   (per batch, NT)
    gemm_tiled<true><<<dim3(SS / BN, SS / BM, BB), blk>>>(
        pG, X2, pA, SS, SS, DD, (ll)SS * DD, (ll)SS * DD, (ll)SS * SS, s, psw, SS);

    // 8. P = softmax(scores) rows, in place
    softmax_rows<<<BSROWS, 256>>>(pA);

    // 9. negVsum[b,:] = -(alpha/S) * sum_k V[b,k,:]
    vsum_part<<<64, 1024>>>(pV, ppart);
    vsum_reduce<<<BB, 1024>>>(ppart, alph, pnegV);

    // 10. out = P @ V + negVsum[b]   (per batch)
    gemm_tiled<false><<<dim3(DD / BN, SS / BM, BB), blk>>>(
        pA, pV, out, SS, DD, SS, (ll)SS * SS, (ll)SS * DD, (ll)SS * DD, 1.f, pnegV, DD);
}